// round 16
// baseline (speedup 1.0000x reference)
#include <cuda_runtime.h>
#include <cstdint>
#include <cuda_bf16.h>
#include <cuda_fp16.h>
#include <mma.h>
#include <math.h>

using namespace nvcuda;

#define SS 4096
#define CC 2048
#define HH 16
#define DD 128
#define EPSF 1.1920929e-07f

// Scratch (no cudaMalloc allowed)
__device__ float    g_q[SS * CC];            // Q fp32 (post norm+rope)
__device__ uint32_t g_k[SS * HH * 64];       // K fp16 packed d-pairs (single)
__device__ uint32_t g_v[SS * HH * 64];       // V fp16 k-pair words [s/2][H][128]
// operands in PADDED TILE-IMAGE layout [tile=row/128][slab=k/32][128 x 40]
#define PADN(r, c) ((size_t)(r) * (c) * 5 / 4)
__device__ __half g_xh[PADN(SS, CC)], g_xl[PADN(SS, CC)];   // x fp16 hi/lo
__device__ __half g_ah[PADN(SS, CC)], g_al[PADN(SS, CC)];   // attn fp16 hi/lo
__device__ __half g_wq[PADN(CC, CC)];                        // weights single fp16
__device__ __half g_wk[PADN(CC, CC)];
__device__ __half g_wv[PADN(CC, CC)];
__device__ __half g_wo[PADN(CC, CC)];

#define TILE_ELEMS 327680u    // 64 slabs * 5120 elems
#define SLAB_ELEMS 5120u      // 128 rows * 40 halves

// ---------------------------------------------------------------------------
// helpers
// ---------------------------------------------------------------------------
__device__ __forceinline__ uint32_t h2pack(float x, float y) {
    __half2 h = __floats2half2_rn(x, y);
    return *(uint32_t*)&h;
}
__device__ __forceinline__ float hres(float x) {
    return x - __half2float(__float2half_rn(x));
}

// fp16 m16n8k16
__device__ __forceinline__ void mma16h(float* c, const uint32_t* a,
                                       uint32_t b0, uint32_t b1) {
    asm volatile(
        "mma.sync.aligned.m16n8k16.row.col.f32.f16.f16.f32 "
        "{%0,%1,%2,%3}, {%4,%5,%6,%7}, {%8,%9}, {%0,%1,%2,%3};\n"
        : "+f"(c[0]), "+f"(c[1]), "+f"(c[2]), "+f"(c[3])
        : "r"(a[0]), "r"(a[1]), "r"(a[2]), "r"(a[3]), "r"(b0), "r"(b1));
}

#define CP16(dst_u32, src_ptr) \
    asm volatile("cp.async.cg.shared.global [%0], [%1], 16;" \
                 :: "r"(dst_u32), "l"(src_ptr) : "memory")
#define CP_COMMIT() asm volatile("cp.async.commit_group;" ::: "memory")

__device__ __forceinline__ void ldsm_x4(uint32_t addr, uint32_t& r0, uint32_t& r1,
                                        uint32_t& r2, uint32_t& r3) {
    asm volatile("ldmatrix.sync.aligned.m8n8.x4.shared.b16 {%0,%1,%2,%3}, [%4];"
                 : "=r"(r0), "=r"(r1), "=r"(r2), "=r"(r3) : "r"(addr));
}

__device__ __forceinline__ uint32_t smem_u32(const void* p) {
    uint32_t a;
    asm("{ .reg .u64 tt; cvta.to.shared.u64 tt, %1; cvt.u32.u64 %0, tt; }"
        : "=r"(a) : "l"(p));
    return a;
}

// --- mbarrier + bulk-DMA primitives ---
#define MBINIT(m, c) \
    asm volatile("mbarrier.init.shared.b64 [%0], %1;" :: "r"(m), "r"(c) : "memory")
#define MBEXPECT(m, b) \
    asm volatile("mbarrier.arrive.expect_tx.shared.b64 _, [%0], %1;" :: "r"(m), "r"(b) : "memory")
#define BULKCP(dst, src, bytes, mbar) \
    asm volatile("cp.async.bulk.shared::cta.global.mbarrier::complete_tx::bytes [%0], [%1], %2, [%3];" \
                 :: "r"(dst), "l"(src), "r"(bytes), "r"(mbar) : "memory")

#define MBWAIT(mbar_addr, parity) do { \
    uint32_t _m = (mbar_addr), _p = (parity), _d; \
    asm volatile( \
        "{\n\t.reg .pred p;\n\t" \
        "mbarrier.try_wait.parity.acquire.cta.shared::cta.b64 p, [%1], %2;\n\t" \
        "selp.b32 %0, 1, 0, p;\n\t}" \
        : "=r"(_d) : "r"(_m), "r"(_p) : "memory"); \
    if (!_d) { \
        asm volatile( \
            "{\n\t.reg .pred P1;\n\t" \
            "WL_%=:\n\t" \
            "mbarrier.try_wait.parity.acquire.cta.shared::cta.b64 P1, [%0], %1, 0x989680;\n\t" \
            "@P1 bra.uni WD_%=;\n\t" \
            "bra.uni WL_%=;\n\t" \
            "WD_%=:\n\t}" \
            :: "r"(_m), "r"(_p) : "memory"); \
    } \
} while (0)

// ---------------------------------------------------------------------------
// splits: fp32 -> fp16 hi(+lo) in padded tile-image layout
// ---------------------------------------------------------------------------
__global__ void split_a16(const float* __restrict__ in,
                          __half* __restrict__ oh, __half* __restrict__ ol)
{
    int idx = blockIdx.x * 256 + threadIdx.x;
    int r  = idx >> 9;
    int kc = (idx & 511) * 4;
    float4 v = *(const float4*)&in[(size_t)r * 2048 + kc];
    uint2 h = make_uint2(h2pack(v.x, v.y), h2pack(v.z, v.w));
    uint2 l = make_uint2(h2pack(hres(v.x), hres(v.y)),
                         h2pack(hres(v.z), hres(v.w)));
    size_t off = (size_t)(r >> 7) * TILE_ELEMS + (size_t)(kc >> 5) * SLAB_ELEMS
               + (r & 127) * 40 + (kc & 31);
    *(uint2*)&oh[off] = h;
    *(uint2*)&ol[off] = l;
}

__global__ void split_w16(const float* __restrict__ in, __half* __restrict__ oh)
{
    int idx = blockIdx.x * 256 + threadIdx.x;
    int r  = idx >> 9;
    int kc = (idx & 511) * 4;
    float4 v = *(const float4*)&in[(size_t)r * 2048 + kc];
    uint2 h = make_uint2(h2pack(v.x, v.y), h2pack(v.z, v.w));
    size_t off = (size_t)(r >> 7) * TILE_ELEMS + (size_t)(kc >> 5) * SLAB_ELEMS
               + (r & 127) * 40 + (kc & 31);
    *(uint2*)&oh[off] = h;
}

// ---------------------------------------------------------------------------
// GEMM (unchanged from R14): A fp16 hi/lo (2-term), B single fp16.
// bulk-DMA 2-stage pipeline; wmma fp16; 128x128x32 tile, 256 thr, 2 CTAs/SM.
// mode 0: fp32 out  1: norm+rope fp32 (Q)  2: norm+rope fp16 K pairs
// mode 3: fp16 V pairs
// ---------------------------------------------------------------------------
__global__ void __launch_bounds__(256, 2)
gemm_blk(const __half* __restrict__ Ahg, const __half* __restrict__ Alg,
         const __half* __restrict__ Bhg,
         const float* __restrict__ bias,
         float* __restrict__ Out,
         uint32_t* __restrict__ outW1,
         const float* __restrict__ normw, const float* __restrict__ rope,
         int mode)
{
    extern __shared__ char smemc[];
    __shared__ uint64_t s_mbar[2];

    const uint32_t sbase = smem_u32(smemc);
    const uint32_t mb0 = smem_u32(&s_mbar[0]);
    const uint32_t mb1 = smem_u32(&s_mbar[1]);

    const int t = threadIdx.x;
    const int warp = t >> 5;
    const int wr = warp >> 2;
    const int wc = warp & 3;
    const int m0 = blockIdx.y * 128;
    const int n0 = blockIdx.x * 128;
    const int hh = blockIdx.x;

    if (t == 0) { MBINIT(mb0, 1); MBINIT(mb1, 1); }
    __syncthreads();

    const __half* pAh = Ahg + (size_t)(m0 >> 7) * TILE_ELEMS;
    const __half* pAl = Alg + (size_t)(m0 >> 7) * TILE_ELEMS;
    const __half* pBh = Bhg + (size_t)(n0 >> 7) * TILE_ELEMS;

    auto fill = [&](int s) {
        int st = s & 1;
        uint32_t fb = st ? mb1 : mb0;
        uint32_t d  = sbase + st * 30720;
        size_t o = (size_t)s * SLAB_ELEMS;
        MBEXPECT(fb, 30720u);
        BULKCP(d,         pAh + o, 10240u, fb);
        BULKCP(d + 10240, pAl + o, 10240u, fb);
        BULKCP(d + 20480, pBh + o, 10240u, fb);
    };

    if (t == 0) { fill(0); fill(1); }

    wmma::fragment<wmma::accumulator, 16, 16, 16, float> cfrag[4][2];
#pragma unroll
    for (int mi = 0; mi < 4; mi++)
#pragma unroll
        for (int nj = 0; nj < 2; nj++) wmma::fill_fragment(cfrag[mi][nj], 0.0f);

    for (int s = 0; s < 64; s++) {
        const int st = s & 1;
        const uint32_t ph = (uint32_t)((s >> 1) & 1);
        MBWAIT(st ? mb1 : mb0, ph);

        __half* Ash = (__half*)(smemc + st * 30720);
        __half* Asl = Ash + 5120;
        __half* Bsh = Ash + 10240;

#pragma unroll
        for (int ks = 0; ks < 2; ks++) {
            wmma::fragment<wmma::matrix_b, 16, 16, 16, half, wmma::col_major> bh[2];
#pragma unroll
            for (int nj = 0; nj < 2; nj++)
                wmma::load_matrix_sync(bh[nj], &Bsh[(wc * 32 + nj * 16) * 40 + ks * 16], 40);
#pragma unroll
            for (int mi = 0; mi < 4; mi++) {
                wmma::fragment<wmma::matrix_a, 16, 16, 16, half, wmma::row_major> ah, al;
                wmma::load_matrix_sync(ah, &Ash[(wr * 64 + mi * 16) * 40 + ks * 16], 40);
                wmma::load_matrix_sync(al, &Asl[(wr * 64 + mi * 16) * 40 + ks * 16], 40);
#pragma unroll
                for (int nj = 0; nj < 2; nj++) {
                    wmma::mma_sync(cfrag[mi][nj], al, bh[nj], cfrag[mi][nj]);
                    wmma::mma_sync(cfrag[mi][nj], ah, bh[nj], cfrag[mi][nj]);
                }
            }
        }
        __syncthreads();
        if (t == 0 && s + 2 < 64) fill(s + 2);
    }

    float* Cs = (float*)smemc;  // [128][132] = 67584 B
#pragma unroll
    for (int mi = 0; mi < 4; mi++)
#pragma unroll
        for (int nj = 0; nj < 2; nj++)
            wmma::store_matrix_sync(&Cs[(wr * 64 + mi * 16) * 132 + wc * 32 + nj * 16],
                                    cfrag[mi][nj], 132, wmma::mem_row_major);
    __syncthreads();

    if (mode == 0) {
#pragma unroll
        for (int i = 0; i < 16; i++) {
            int idx = i * 256 + t;
            int r = idx >> 5, c4 = (idx & 31) * 4;
            float4 cv = *(float4*)&Cs[r * 132 + c4];
            float4 bb = *(const float4*)&bias[n0 + c4];
            cv.x += bb.x; cv.y += bb.y; cv.z += bb.z; cv.w += bb.w;
            *(float4*)&Out[(size_t)(m0 + r) * CC + n0 + c4] = cv;
        }
    } else if (mode == 3) {
        __half* vh = (__half*)outW1;
#pragma unroll
        for (int i = 0; i < 16; i++) {
            int idx = i * 256 + t;
            int r = idx >> 5, c4 = (idx & 31) * 4;
            float4 cv = *(float4*)&Cs[r * 132 + c4];
            float4 bb = *(const float4*)&bias[n0 + c4];
            cv.x += bb.x; cv.y += bb.y; cv.z += bb.z; cv.w += bb.w;
            int sidx = m0 + r;
            size_t wb = ((size_t)(sidx >> 1) * HH + hh) * 128;
            float vals[4] = {cv.x, cv.y, cv.z, cv.w};
#pragma unroll
            for (int e = 0; e < 4; e++) {
                int d = c4 + e;
                int dp = (d & 7) * 16 + (d >> 3);
                vh[(wb + dp) * 2 + (sidx & 1)] = __float2half_rn(vals[e]);
            }
        }
    } else {
        const int r = t >> 1, half_ = t & 1;
        const int s = m0 + r;
        float* row = &Cs[r * 132 + half_ * 64];
        const float* bias_h = &bias[n0 + half_ * 64];
        float ssq = 0.0f;
#pragma unroll
        for (int j = 0; j < 16; j++) {
            float4 c = ((float4*)row)[j];
            float4 bb = ((const float4*)bias_h)[j];
            c.x += bb.x; c.y += bb.y; c.z += bb.z; c.w += bb.w;
            ((float4*)row)[j] = c;
            ssq += c.x * c.x + c.y * c.y + c.z * c.z + c.w * c.w;
        }
        ssq += __shfl_xor_sync(0xffffffffu, ssq, 1);
        float inv = rsqrtf(ssq * (1.0f / 128.0f) + EPSF);
        const float* wv = &normw[half_ * 64];
        const float* rp = &rope[(size_t)s * 256 + half_ * 128];
        float* outp = &Out[(size_t)(m0 + r) * CC + n0 + half_ * 64];
#pragma unroll
        for (int j = 0; j < 16; j++) {
            float4 c = ((float4*)row)[j];
            float4 ww = ((const float4*)wv)[j];
            float x0 = c.x * inv * ww.x;
            float x1 = c.y * inv * ww.y;
            float x2 = c.z * inv * ww.z;
            float x3 = c.w * inv * ww.w;
            float4 rA = ((const float4*)rp)[2 * j];
            float4 rB = ((const float4*)rp)[2 * j + 1];
            float4 ov;
            ov.x = rA.x * x0 + rA.y * x1;
            ov.y = rA.z * x0 + rA.w * x1;
            ov.z = rB.x * x2 + rB.y * x3;
            ov.w = rB.z * x2 + rB.w * x3;
            if (mode == 1) {
                ((float4*)outp)[j] = ov;
            } else {
                size_t kb = ((size_t)s * HH + hh) * 64 + half_ * 32 + j * 2;
                uint2 w = make_uint2(h2pack(ov.x, ov.y), h2pack(ov.z, ov.w));
                *(uint2*)&outW1[kb] = w;
            }
        }
    }
}

// ---------------------------------------------------------------------------
// Flash attention, occupancy-2 version:
//  - P never touches smem (PV A-fragments are thread-local by layout identity)
//  - Q hi in regs (32), Q lo in smem (thread-private uint4 slots)
//  - smem words: Qlo [0,8192); KsH 8192+st*4352 [64][68]; Vs 16896+st*4224
//    [32][132]  -> 25344 w = 101376 B; 2 CTAs/SM.
// Arithmetic bit-identical to R14.
// ---------------------------------------------------------------------------
__global__ void __launch_bounds__(256, 2)
flash_attn_tc(const float* __restrict__ q,
              const uint32_t* __restrict__ kk,
              const uint32_t* __restrict__ vv,
              __half* __restrict__ oh, __half* __restrict__ ol)
{
    extern __shared__ uint32_t usm[];
    uint32_t sbase = smem_u32(usm);

    const int h  = blockIdx.y;
    const int q0 = blockIdx.x * 128;
    const int t  = threadIdx.x;
    const int warp = t >> 5;
    const int lane = t & 31;
    const int g   = lane >> 2;
    const int tig = lane & 3;
    const int r0 = warp * 16 + g;
    const int r1 = r0 + 8;
    const float scale = 0.08838834764831845f;

    const int rowsel = (lane & 7) + ((lane >> 4) & 1) * 8;
    const int halfw  = ((lane >> 3) & 1) * 4;

    // Q -> fp16 hi regs + residual lo in smem (thread-private uint4 slots)
    uint32_t qh[8][4];
    {
        const float* qr0 = &q[((size_t)(q0 + r0) * HH + h) * DD];
        const float* qr1 = &q[((size_t)(q0 + r1) * HH + h) * DD];
#pragma unroll
        for (int ks = 0; ks < 8; ks++) {
            int c = ks * 16 + 2 * tig;
            float a0 = qr0[c] * scale,     a1 = qr0[c + 1] * scale;
            float b0 = qr1[c] * scale,     b1 = qr1[c + 1] * scale;
            float c0 = qr0[c + 8] * scale, c1 = qr0[c + 9] * scale;
            float d0 = qr1[c + 8] * scale, d1 = qr1[c + 9] * scale;
            qh[ks][0] = h2pack(a0, a1);
            qh[ks][1] = h2pack(b0, b1);
            qh[ks][2] = h2pack(c0, c1);
            qh[ks][3] = h2pack(d0, d1);
            uint4 qlv = make_uint4(h2pack(hres(a0), hres(a1)),
                                   h2pack(hres(b0), hres(b1)),
                                   h2pack(hres(c0), hres(c1)),
                                   h2pack(hres(d0), hres(d1)));
            *(uint4*)&usm[(ks * 256 + t) * 4] = qlv;
        }
    }

    float m0r = -1e30f, m1r = -1e30f, l0 = 0.0f, l1 = 0.0f;
    float oacc[16][4];
#pragma unroll
    for (int j = 0; j < 16; j++)
#pragma unroll
        for (int e = 0; e < 4; e++) oacc[j][e] = 0.0f;

    auto fill = [&](int st, int kv) {
        const uint32_t dKH = sbase + (8192 + st * 4352) * 4;
        const uint32_t dV  = sbase + (16896 + st * 4224) * 4;
#pragma unroll
        for (int i = 0; i < 4; i++) {
            int c = i * 256 + t; int r = c >> 4, w = (c & 15) * 4;
            CP16(dKH + (uint32_t)(r * 68 + w) * 4,
                 &kk[((size_t)(kv + r) * HH + h) * 64 + w]);
        }
#pragma unroll
        for (int i = 0; i < 4; i++) {
            int c = i * 256 + t; int pr = c >> 5, w = (c & 31) * 4;
            CP16(dV + (uint32_t)(pr * 132 + w) * 4,
                 &vv[((size_t)((kv >> 1) + pr) * HH + h) * 128 + w]);
        }
    };

    fill(0, 0);
    CP_COMMIT();

    for (int kv0 = 0; kv0 < SS; kv0 += 64) {
        const int st = (kv0 >> 6) & 1;
        const bool more = (kv0 + 64) < SS;

        if (more) { fill(st ^ 1, kv0 + 64); CP_COMMIT(); }

        if (more) { asm volatile("cp.async.wait_group 1;" ::: "memory"); }
        else      { asm volatile("cp.async.wait_group 0;" ::: "memory"); }
        __syncthreads();

        const uint32_t bKH = sbase + (8192 + st * 4352) * 4;
        uint32_t* VsSt = usm + 16896 + st * 4224;

        float sacc[8][4];
#pragma unroll
        for (int j = 0; j < 8; j++)
#pragma unroll
            for (int e = 0; e < 4; e++) sacc[j][e] = 0.0f;

#pragma unroll
        for (int ks = 0; ks < 8; ks++) {
            uint4 qlv = *(uint4*)&usm[(ks * 256 + t) * 4];
            uint32_t ql[4] = {qlv.x, qlv.y, qlv.z, qlv.w};
#pragma unroll
            for (int jp = 0; jp < 4; jp++) {
                uint32_t woff = (uint32_t)((jp * 16 + rowsel) * 68 + ks * 8 + halfw) * 4;
                uint32_t h0, h1, h2, h3;
                ldsm_x4(bKH + woff, h0, h1, h2, h3);
                mma16h(sacc[2 * jp],     ql,     h0, h1);
                mma16h(sacc[2 * jp],     qh[ks], h0, h1);
                mma16h(sacc[2 * jp + 1], ql,     h2, h3);
                mma16h(sacc[2 * jp + 1], qh[ks], h2, h3);
            }
        }

        float rmax0 = -1e30f, rmax1 = -1e30f;
#pragma unroll
        for (int j = 0; j < 8; j++) {
            rmax0 = fmaxf(rmax0, fmaxf(sacc[j][0], sacc[j][1]));
            rmax1 = fmaxf(rmax1, fmaxf(sacc[j][2], sacc[j][3]));
        }
#pragma unroll
        for (int off = 1; off < 4; off <<= 1) {
            rmax0 = fmaxf(rmax0, __shfl_xor_sync(0xffffffffu, rmax0, off));
            rmax1 = fmaxf(rmax1, __shfl_xor_sync(0xffffffffu, rmax1, off));
        }
        float mn0 = fmaxf(m0r, rmax0);
        float mn1 = fmaxf(m1r, rmax1);
        float cr0 = __expf(m0r - mn0);
        float cr1 = __expf(m1r - mn1);
        float rs0 = 0.0f, rs1 = 0.0f;
        uint32_t p0[8], p1[8];     // P pairs held in registers (thread-local PV A)
#pragma unroll
        for (int j = 0; j < 8; j++) {
            float e0 = __expf(sacc[j][0] - mn0);
            float e1 = __expf(sacc[j][1] - mn0);
            float e2 = __expf(sacc[j][2] - mn1);
            float e3 = __expf(sacc[j][3] - mn1);
            rs0 += e0 + e1;
            rs1 += e2 + e3;
            p0[j] = h2pack(e0, e1);
            p1[j] = h2pack(e2, e3);
        }
#pragma unroll
        for (int off = 1; off < 4; off <<= 1) {
            rs0 += __shfl_xor_sync(0xffffffffu, rs0, off);
            rs1 += __shfl_xor_sync(0xffffffffu, rs1, off);
        }
        l0 = l0 * cr0 + rs0;
        l1 = l1 * cr1 + rs1;
        m0r = mn0;
        m1r = mn1;
#pragma unroll
        for (int j = 0; j < 16; j++) {
            oacc[j][0] *= cr0; oacc[j][1] *= cr0;
            oacc[j][2] *= cr1; oacc[j][3] *= cr1;
        }

        // ---- PV: fp16 m16n8k16, k=64 -> 4 k-steps; A from registers ----
#pragma unroll
        for (int kc = 0; kc < 4; kc++) {
            uint32_t a[4];
            a[0] = p0[2 * kc];
            a[1] = p1[2 * kc];
            a[2] = p0[2 * kc + 1];
            a[3] = p1[2 * kc + 1];
            const int row0 = kc * 8 + tig, row1 = row0 + 4;
            uint32_t vb0[16], vb1[16];
#pragma unroll
            for (int jq = 0; jq < 4; jq++) {
                *(uint4*)&vb0[jq * 4] = *(uint4*)&VsSt[row0 * 132 + g * 16 + jq * 4];
                *(uint4*)&vb1[jq * 4] = *(uint4*)&VsSt[row1 * 132 + g * 16 + jq * 4];
            }
#pragma unroll
            for (int j = 0; j < 16; j++)
                mma16h(oacc[j], a, vb0[j], vb1[j]);
        }
        __syncthreads();
    }

    // epilogue: write pre-split fp16 hi/lo tile-image directly
    float inv0 = 1.0f / l0, inv1 = 1.0f / l1;
#pragma unroll
    for (int j = 0; j < 16; j++) {
        int c = h * 128 + j * 8 + 2 * tig;
        float a0 = oacc[j][0] * inv0, a1 = oacc[j][1] * inv0;
        float b0v = oacc[j][2] * inv1, b1v = oacc[j][3] * inv1;
        size_t cb = (size_t)(q0 >> 7) * TILE_ELEMS + (size_t)(c >> 5) * SLAB_ELEMS
                  + (c & 31);
        size_t off0 = cb + r0 * 40;
        size_t off1 = cb + r1 * 40;
        *(uint32_t*)&oh[off0] = h2pack(a0, a1);
        *(uint32_t*)&ol[off0] = h2pack(hres(a0), hres(a1));
        *(uint32_t*)&oh[off1] = h2pack(b0v, b1v);
        *(uint32_t*)&ol[off1] = h2pack(hres(b0v), hres(b1v));
    }
}

// ---------------------------------------------------------------------------
extern "C" void kernel_launch(void* const* d_in, const int* in_sizes, int n_in,
                              void* d_out, int out_size)
{
    const float* x    = (const float*)d_in[0];
    const float* rope = (const float*)d_in[1];
    const float* Wq   = (const float*)d_in[2];
    const float* bq   = (const float*)d_in[3];
    const float* Wk   = (const float*)d_in[4];
    const float* bk   = (const float*)d_in[5];
    const float* Wv   = (const float*)d_in[6];
    const float* bv   = (const float*)d_in[7];
    const float* qn_w = (const float*)d_in[8];
    const float* kn_w = (const float*)d_in[9];
    const float* Wo   = (const float*)d_in[10];
    const float* bo   = (const float*)d_in[11];
    float* out = (float*)d_out;

    float* qp;
    uint32_t *kp, *vp;
    __half *xh, *xl, *ah, *al, *wq, *wk, *wv, *wo;
    cudaGetSymbolAddress((void**)&qp, g_q);
    cudaGetSymbolAddress((void**)&kp, g_k);
    cudaGetSymbolAddress((void**)&vp, g_v);
    cudaGetSymbolAddress((void**)&xh, g_xh);
    cudaGetSymbolAddress((void**)&xl, g_xl);
    cudaGetSymbolAddress((void**)&ah, g_ah);
    cudaGetSymbolAddress((void**)&al, g_al);
    cudaGetSymbolAddress((void**)&wq, g_wq);
    cudaGetSymbolAddress((void**)&wk, g_wk);
    cudaGetSymbolAddress((void**)&wv, g_wv);
    cudaGetSymbolAddress((void**)&wo, g_wo);

    const int smem_gemm = 67584;   // max(2*30720 stages, Cs 128*132*4)
    const int smem_attn = 101376;  // Qlo 32768 + K 2*17408 + V 2*16896
    cudaFuncSetAttribute(gemm_blk, cudaFuncAttributeMaxDynamicSharedMemorySize,
                         smem_gemm);
    cudaFuncSetAttribute(flash_attn_tc, cudaFuncAttributeMaxDynamicSharedMemorySize,
                         smem_attn);

    split_a16<<<8192, 256>>>(x, xh, xl);
    split_w16<<<4096, 256>>>(Wq, wq);
    split_w16<<<4096, 256>>>(Wk, wk);
    split_w16<<<4096, 256>>>(Wv, wv);
    split_w16<<<4096, 256>>>(Wo, wo);

    dim3 ggrid(CC / 128, SS / 128);
    gemm_blk<<<ggrid, 256, smem_gemm>>>(xh, xl, wq, bq, qp, nullptr, qn_w, rope, 1);
    gemm_blk<<<ggrid, 256, smem_gemm>>>(xh, xl, wk, bk, nullptr, kp, kn_w, rope, 2);
    gemm_blk<<<ggrid, 256, smem_gemm>>>(xh, xl, wv, bv, nullptr, vp, nullptr, nullptr, 3);

    dim3 agrid(SS / 128, HH);
    flash_attn_tc<<<agrid, 256, smem_attn>>>(qp, kp, vp, ah, al);

    gemm_blk<<<ggrid, 256, smem_gemm>>>(ah, al, wo, bo, out, nullptr, nullptr, nullptr, 0);
}

// round 17
// speedup vs baseline: 1.0832x; 1.0832x over previous
#include <cuda_runtime.h>
#include <cstdint>
#include <cuda_bf16.h>
#include <cuda_fp16.h>
#include <mma.h>
#include <math.h>

using namespace nvcuda;

#define SS 4096
#define CC 2048
#define HH 16
#define DD 128
#define EPSF 1.1920929e-07f

// Scratch (no cudaMalloc allowed)
__device__ float    g_q[SS * CC];            // Q fp32 (post norm+rope)
__device__ uint32_t g_k[SS * HH * 64];       // K fp16 packed d-pairs (single)
__device__ uint32_t g_v[SS * HH * 64];       // V fp16 k-pair words [s/2][H][128]
// operands in PADDED TILE-IMAGE layout [tile=row/128][slab=k/32][128 x 40]
#define PADN(r, c) ((size_t)(r) * (c) * 5 / 4)
__device__ __half g_xh[PADN(SS, CC)], g_xl[PADN(SS, CC)];   // x fp16 hi/lo
__device__ __half g_ah[PADN(SS, CC)], g_al[PADN(SS, CC)];   // attn fp16 hi/lo
__device__ __half g_wq[PADN(CC, CC)];                        // weights single fp16
__device__ __half g_wk[PADN(CC, CC)];
__device__ __half g_wv[PADN(CC, CC)];
__device__ __half g_wo[PADN(CC, CC)];

#define TILE_ELEMS 327680u    // 64 slabs * 5120 elems
#define SLAB_ELEMS 5120u      // 128 rows * 40 halves

// ---------------------------------------------------------------------------
// helpers
// ---------------------------------------------------------------------------
__device__ __forceinline__ uint32_t h2pack(float x, float y) {
    __half2 h = __floats2half2_rn(x, y);
    return *(uint32_t*)&h;
}
__device__ __forceinline__ float hres(float x) {
    return x - __half2float(__float2half_rn(x));
}

// fp16 m16n8k16
__device__ __forceinline__ void mma16h(float* c, const uint32_t* a,
                                       uint32_t b0, uint32_t b1) {
    asm volatile(
        "mma.sync.aligned.m16n8k16.row.col.f32.f16.f16.f32 "
        "{%0,%1,%2,%3}, {%4,%5,%6,%7}, {%8,%9}, {%0,%1,%2,%3};\n"
        : "+f"(c[0]), "+f"(c[1]), "+f"(c[2]), "+f"(c[3])
        : "r"(a[0]), "r"(a[1]), "r"(a[2]), "r"(a[3]), "r"(b0), "r"(b1));
}

#define CP16(dst_u32, src_ptr) \
    asm volatile("cp.async.cg.shared.global [%0], [%1], 16;" \
                 :: "r"(dst_u32), "l"(src_ptr) : "memory")
#define CP_COMMIT() asm volatile("cp.async.commit_group;" ::: "memory")

__device__ __forceinline__ void ldsm_x4(uint32_t addr, uint32_t& r0, uint32_t& r1,
                                        uint32_t& r2, uint32_t& r3) {
    asm volatile("ldmatrix.sync.aligned.m8n8.x4.shared.b16 {%0,%1,%2,%3}, [%4];"
                 : "=r"(r0), "=r"(r1), "=r"(r2), "=r"(r3) : "r"(addr));
}

__device__ __forceinline__ uint32_t smem_u32(const void* p) {
    uint32_t a;
    asm("{ .reg .u64 tt; cvta.to.shared.u64 tt, %1; cvt.u32.u64 %0, tt; }"
        : "=r"(a) : "l"(p));
    return a;
}

// --- mbarrier + bulk-DMA primitives ---
#define MBINIT(m, c) \
    asm volatile("mbarrier.init.shared.b64 [%0], %1;" :: "r"(m), "r"(c) : "memory")
#define MBEXPECT(m, b) \
    asm volatile("mbarrier.arrive.expect_tx.shared.b64 _, [%0], %1;" :: "r"(m), "r"(b) : "memory")
#define BULKCP(dst, src, bytes, mbar) \
    asm volatile("cp.async.bulk.shared::cta.global.mbarrier::complete_tx::bytes [%0], [%1], %2, [%3];" \
                 :: "r"(dst), "l"(src), "r"(bytes), "r"(mbar) : "memory")

#define MBWAIT(mbar_addr, parity) do { \
    uint32_t _m = (mbar_addr), _p = (parity), _d; \
    asm volatile( \
        "{\n\t.reg .pred p;\n\t" \
        "mbarrier.try_wait.parity.acquire.cta.shared::cta.b64 p, [%1], %2;\n\t" \
        "selp.b32 %0, 1, 0, p;\n\t}" \
        : "=r"(_d) : "r"(_m), "r"(_p) : "memory"); \
    if (!_d) { \
        asm volatile( \
            "{\n\t.reg .pred P1;\n\t" \
            "WL_%=:\n\t" \
            "mbarrier.try_wait.parity.acquire.cta.shared::cta.b64 P1, [%0], %1, 0x989680;\n\t" \
            "@P1 bra.uni WD_%=;\n\t" \
            "bra.uni WL_%=;\n\t" \
            "WD_%=:\n\t}" \
            :: "r"(_m), "r"(_p) : "memory"); \
    } \
} while (0)

// ---------------------------------------------------------------------------
// splits: fp32 -> fp16 hi(+lo) in padded tile-image layout
// ---------------------------------------------------------------------------
__global__ void split_a16(const float* __restrict__ in,
                          __half* __restrict__ oh, __half* __restrict__ ol)
{
    int idx = blockIdx.x * 256 + threadIdx.x;
    int r  = idx >> 9;
    int kc = (idx & 511) * 4;
    float4 v = *(const float4*)&in[(size_t)r * 2048 + kc];
    uint2 h = make_uint2(h2pack(v.x, v.y), h2pack(v.z, v.w));
    uint2 l = make_uint2(h2pack(hres(v.x), hres(v.y)),
                         h2pack(hres(v.z), hres(v.w)));
    size_t off = (size_t)(r >> 7) * TILE_ELEMS + (size_t)(kc >> 5) * SLAB_ELEMS
               + (r & 127) * 40 + (kc & 31);
    *(uint2*)&oh[off] = h;
    *(uint2*)&ol[off] = l;
}

__global__ void split_w16(const float* __restrict__ in, __half* __restrict__ oh)
{
    int idx = blockIdx.x * 256 + threadIdx.x;
    int r  = idx >> 9;
    int kc = (idx & 511) * 4;
    float4 v = *(const float4*)&in[(size_t)r * 2048 + kc];
    uint2 h = make_uint2(h2pack(v.x, v.y), h2pack(v.z, v.w));
    size_t off = (size_t)(r >> 7) * TILE_ELEMS + (size_t)(kc >> 5) * SLAB_ELEMS
               + (r & 127) * 40 + (kc & 31);
    *(uint2*)&oh[off] = h;
}

// ---------------------------------------------------------------------------
// GEMM (unchanged from R14): A fp16 hi/lo (2-term), B single fp16.
// bulk-DMA 2-stage pipeline; wmma fp16; 128x128x32 tile, 256 thr, 2 CTAs/SM.
// mode 0: fp32 out  1: norm+rope fp32 (Q)  2: norm+rope fp16 K pairs
// mode 3: fp16 V pairs
// ---------------------------------------------------------------------------
__global__ void __launch_bounds__(256, 2)
gemm_blk(const __half* __restrict__ Ahg, const __half* __restrict__ Alg,
         const __half* __restrict__ Bhg,
         const float* __restrict__ bias,
         float* __restrict__ Out,
         uint32_t* __restrict__ outW1,
         const float* __restrict__ normw, const float* __restrict__ rope,
         int mode)
{
    extern __shared__ char smemc[];
    __shared__ uint64_t s_mbar[2];

    const uint32_t sbase = smem_u32(smemc);
    const uint32_t mb0 = smem_u32(&s_mbar[0]);
    const uint32_t mb1 = smem_u32(&s_mbar[1]);

    const int t = threadIdx.x;
    const int warp = t >> 5;
    const int wr = warp >> 2;
    const int wc = warp & 3;
    const int m0 = blockIdx.y * 128;
    const int n0 = blockIdx.x * 128;
    const int hh = blockIdx.x;

    if (t == 0) { MBINIT(mb0, 1); MBINIT(mb1, 1); }
    __syncthreads();

    const __half* pAh = Ahg + (size_t)(m0 >> 7) * TILE_ELEMS;
    const __half* pAl = Alg + (size_t)(m0 >> 7) * TILE_ELEMS;
    const __half* pBh = Bhg + (size_t)(n0 >> 7) * TILE_ELEMS;

    auto fill = [&](int s) {
        int st = s & 1;
        uint32_t fb = st ? mb1 : mb0;
        uint32_t d  = sbase + st * 30720;
        size_t o = (size_t)s * SLAB_ELEMS;
        MBEXPECT(fb, 30720u);
        BULKCP(d,         pAh + o, 10240u, fb);
        BULKCP(d + 10240, pAl + o, 10240u, fb);
        BULKCP(d + 20480, pBh + o, 10240u, fb);
    };

    if (t == 0) { fill(0); fill(1); }

    wmma::fragment<wmma::accumulator, 16, 16, 16, float> cfrag[4][2];
#pragma unroll
    for (int mi = 0; mi < 4; mi++)
#pragma unroll
        for (int nj = 0; nj < 2; nj++) wmma::fill_fragment(cfrag[mi][nj], 0.0f);

    for (int s = 0; s < 64; s++) {
        const int st = s & 1;
        const uint32_t ph = (uint32_t)((s >> 1) & 1);
        MBWAIT(st ? mb1 : mb0, ph);

        __half* Ash = (__half*)(smemc + st * 30720);
        __half* Asl = Ash + 5120;
        __half* Bsh = Ash + 10240;

#pragma unroll
        for (int ks = 0; ks < 2; ks++) {
            wmma::fragment<wmma::matrix_b, 16, 16, 16, half, wmma::col_major> bh[2];
#pragma unroll
            for (int nj = 0; nj < 2; nj++)
                wmma::load_matrix_sync(bh[nj], &Bsh[(wc * 32 + nj * 16) * 40 + ks * 16], 40);
#pragma unroll
            for (int mi = 0; mi < 4; mi++) {
                wmma::fragment<wmma::matrix_a, 16, 16, 16, half, wmma::row_major> ah, al;
                wmma::load_matrix_sync(ah, &Ash[(wr * 64 + mi * 16) * 40 + ks * 16], 40);
                wmma::load_matrix_sync(al, &Asl[(wr * 64 + mi * 16) * 40 + ks * 16], 40);
#pragma unroll
                for (int nj = 0; nj < 2; nj++) {
                    wmma::mma_sync(cfrag[mi][nj], al, bh[nj], cfrag[mi][nj]);
                    wmma::mma_sync(cfrag[mi][nj], ah, bh[nj], cfrag[mi][nj]);
                }
            }
        }
        __syncthreads();
        if (t == 0 && s + 2 < 64) fill(s + 2);
    }

    float* Cs = (float*)smemc;  // [128][132] = 67584 B
#pragma unroll
    for (int mi = 0; mi < 4; mi++)
#pragma unroll
        for (int nj = 0; nj < 2; nj++)
            wmma::store_matrix_sync(&Cs[(wr * 64 + mi * 16) * 132 + wc * 32 + nj * 16],
                                    cfrag[mi][nj], 132, wmma::mem_row_major);
    __syncthreads();

    if (mode == 0) {
#pragma unroll
        for (int i = 0; i < 16; i++) {
            int idx = i * 256 + t;
            int r = idx >> 5, c4 = (idx & 31) * 4;
            float4 cv = *(float4*)&Cs[r * 132 + c4];
            float4 bb = *(const float4*)&bias[n0 + c4];
            cv.x += bb.x; cv.y += bb.y; cv.z += bb.z; cv.w += bb.w;
            *(float4*)&Out[(size_t)(m0 + r) * CC + n0 + c4] = cv;
        }
    } else if (mode == 3) {
        __half* vh = (__half*)outW1;
#pragma unroll
        for (int i = 0; i < 16; i++) {
            int idx = i * 256 + t;
            int r = idx >> 5, c4 = (idx & 31) * 4;
            float4 cv = *(float4*)&Cs[r * 132 + c4];
            float4 bb = *(const float4*)&bias[n0 + c4];
            cv.x += bb.x; cv.y += bb.y; cv.z += bb.z; cv.w += bb.w;
            int sidx = m0 + r;
            size_t wb = ((size_t)(sidx >> 1) * HH + hh) * 128;
            float vals[4] = {cv.x, cv.y, cv.z, cv.w};
#pragma unroll
            for (int e = 0; e < 4; e++) {
                int d = c4 + e;
                int dp = (d & 7) * 16 + (d >> 3);
                vh[(wb + dp) * 2 + (sidx & 1)] = __float2half_rn(vals[e]);
            }
        }
    } else {
        const int r = t >> 1, half_ = t & 1;
        const int s = m0 + r;
        float* row = &Cs[r * 132 + half_ * 64];
        const float* bias_h = &bias[n0 + half_ * 64];
        float ssq = 0.0f;
#pragma unroll
        for (int j = 0; j < 16; j++) {
            float4 c = ((float4*)row)[j];
            float4 bb = ((const float4*)bias_h)[j];
            c.x += bb.x; c.y += bb.y; c.z += bb.z; c.w += bb.w;
            ((float4*)row)[j] = c;
            ssq += c.x * c.x + c.y * c.y + c.z * c.z + c.w * c.w;
        }
        ssq += __shfl_xor_sync(0xffffffffu, ssq, 1);
        float inv = rsqrtf(ssq * (1.0f / 128.0f) + EPSF);
        const float* wv = &normw[half_ * 64];
        const float* rp = &rope[(size_t)s * 256 + half_ * 128];
        float* outp = &Out[(size_t)(m0 + r) * CC + n0 + half_ * 64];
#pragma unroll
        for (int j = 0; j < 16; j++) {
            float4 c = ((float4*)row)[j];
            float4 ww = ((const float4*)wv)[j];
            float x0 = c.x * inv * ww.x;
            float x1 = c.y * inv * ww.y;
            float x2 = c.z * inv * ww.z;
            float x3 = c.w * inv * ww.w;
            float4 rA = ((const float4*)rp)[2 * j];
            float4 rB = ((const float4*)rp)[2 * j + 1];
            float4 ov;
            ov.x = rA.x * x0 + rA.y * x1;
            ov.y = rA.z * x0 + rA.w * x1;
            ov.z = rB.x * x2 + rB.y * x3;
            ov.w = rB.z * x2 + rB.w * x3;
            if (mode == 1) {
                ((float4*)outp)[j] = ov;
            } else {
                size_t kb = ((size_t)s * HH + hh) * 64 + half_ * 32 + j * 2;
                uint2 w = make_uint2(h2pack(ov.x, ov.y), h2pack(ov.z, ov.w));
                *(uint2*)&outW1[kb] = w;
            }
        }
    }
}

// ---------------------------------------------------------------------------
// Flash attention (R14 base + P-in-registers, occ 1, no reg cap):
//  - QK fp16 2-term: Q hi+lo in registers, K single fp16 via ldmatrix
//  - P pairs stay in registers (PV A-fragments are thread-local by layout)
//  - PV fp16; output written as pre-split fp16 hi/lo tile-image
// smem words: KsH st*4352 [64][68]; Vs 8704+st*4224 [32][132].
// Total 17152 w = 68608 B. Arithmetic bit-identical to R14.
// ---------------------------------------------------------------------------
__global__ void __launch_bounds__(256, 1)
flash_attn_tc(const float* __restrict__ q,
              const uint32_t* __restrict__ kk,
              const uint32_t* __restrict__ vv,
              __half* __restrict__ oh, __half* __restrict__ ol)
{
    extern __shared__ uint32_t usm[];
    uint32_t sbase = smem_u32(usm);

    const int h  = blockIdx.y;
    const int q0 = blockIdx.x * 128;
    const int t  = threadIdx.x;
    const int warp = t >> 5;
    const int lane = t & 31;
    const int g   = lane >> 2;
    const int tig = lane & 3;
    const int r0 = warp * 16 + g;
    const int r1 = r0 + 8;
    const float scale = 0.08838834764831845f;

    const int rowsel = (lane & 7) + ((lane >> 4) & 1) * 8;
    const int halfw  = ((lane >> 3) & 1) * 4;

    // Q -> fp16 hi + residual lo in registers (pre-scaled)
    uint32_t qh[8][4], ql[8][4];
    {
        const float* qr0 = &q[((size_t)(q0 + r0) * HH + h) * DD];
        const float* qr1 = &q[((size_t)(q0 + r1) * HH + h) * DD];
#pragma unroll
        for (int ks = 0; ks < 8; ks++) {
            int c = ks * 16 + 2 * tig;
            float a0 = qr0[c] * scale,     a1 = qr0[c + 1] * scale;
            float b0 = qr1[c] * scale,     b1 = qr1[c + 1] * scale;
            float c0 = qr0[c + 8] * scale, c1 = qr0[c + 9] * scale;
            float d0 = qr1[c + 8] * scale, d1 = qr1[c + 9] * scale;
            qh[ks][0] = h2pack(a0, a1);
            qh[ks][1] = h2pack(b0, b1);
            qh[ks][2] = h2pack(c0, c1);
            qh[ks][3] = h2pack(d0, d1);
            ql[ks][0] = h2pack(hres(a0), hres(a1));
            ql[ks][1] = h2pack(hres(b0), hres(b1));
            ql[ks][2] = h2pack(hres(c0), hres(c1));
            ql[ks][3] = h2pack(hres(d0), hres(d1));
        }
    }

    float m0r = -1e30f, m1r = -1e30f, l0 = 0.0f, l1 = 0.0f;
    float oacc[16][4];
#pragma unroll
    for (int j = 0; j < 16; j++)
#pragma unroll
        for (int e = 0; e < 4; e++) oacc[j][e] = 0.0f;

    auto fill = [&](int st, int kv) {
        const uint32_t dKH = sbase + (st * 4352) * 4;
        const uint32_t dV  = sbase + (8704 + st * 4224) * 4;
#pragma unroll
        for (int i = 0; i < 4; i++) {
            int c = i * 256 + t; int r = c >> 4, w = (c & 15) * 4;
            CP16(dKH + (uint32_t)(r * 68 + w) * 4,
                 &kk[((size_t)(kv + r) * HH + h) * 64 + w]);
        }
#pragma unroll
        for (int i = 0; i < 4; i++) {
            int c = i * 256 + t; int pr = c >> 5, w = (c & 31) * 4;
            CP16(dV + (uint32_t)(pr * 132 + w) * 4,
                 &vv[((size_t)((kv >> 1) + pr) * HH + h) * 128 + w]);
        }
    };

    fill(0, 0);
    CP_COMMIT();

    for (int kv0 = 0; kv0 < SS; kv0 += 64) {
        const int st = (kv0 >> 6) & 1;
        const bool more = (kv0 + 64) < SS;

        if (more) { fill(st ^ 1, kv0 + 64); CP_COMMIT(); }

        if (more) { asm volatile("cp.async.wait_group 1;" ::: "memory"); }
        else      { asm volatile("cp.async.wait_group 0;" ::: "memory"); }
        __syncthreads();

        const uint32_t bKH = sbase + (st * 4352) * 4;
        uint32_t* VsSt = usm + 8704 + st * 4224;

        float sacc[8][4];
#pragma unroll
        for (int j = 0; j < 8; j++)
#pragma unroll
            for (int e = 0; e < 4; e++) sacc[j][e] = 0.0f;

#pragma unroll
        for (int ks = 0; ks < 8; ks++) {
#pragma unroll
            for (int jp = 0; jp < 4; jp++) {
                uint32_t woff = (uint32_t)((jp * 16 + rowsel) * 68 + ks * 8 + halfw) * 4;
                uint32_t h0, h1, h2, h3;
                ldsm_x4(bKH + woff, h0, h1, h2, h3);
                mma16h(sacc[2 * jp],     ql[ks], h0, h1);
                mma16h(sacc[2 * jp],     qh[ks], h0, h1);
                mma16h(sacc[2 * jp + 1], ql[ks], h2, h3);
                mma16h(sacc[2 * jp + 1], qh[ks], h2, h3);
            }
        }

        float rmax0 = -1e30f, rmax1 = -1e30f;
#pragma unroll
        for (int j = 0; j < 8; j++) {
            rmax0 = fmaxf(rmax0, fmaxf(sacc[j][0], sacc[j][1]));
            rmax1 = fmaxf(rmax1, fmaxf(sacc[j][2], sacc[j][3]));
        }
#pragma unroll
        for (int off = 1; off < 4; off <<= 1) {
            rmax0 = fmaxf(rmax0, __shfl_xor_sync(0xffffffffu, rmax0, off));
            rmax1 = fmaxf(rmax1, __shfl_xor_sync(0xffffffffu, rmax1, off));
        }
        float mn0 = fmaxf(m0r, rmax0);
        float mn1 = fmaxf(m1r, rmax1);
        float cr0 = __expf(m0r - mn0);
        float cr1 = __expf(m1r - mn1);
        float rs0 = 0.0f, rs1 = 0.0f;
        uint32_t p0[8], p1[8];     // P pairs in registers (thread-local PV A)
#pragma unroll
        for (int j = 0; j < 8; j++) {
            float e0 = __expf(sacc[j][0] - mn0);
            float e1 = __expf(sacc[j][1] - mn0);
            float e2 = __expf(sacc[j][2] - mn1);
            float e3 = __expf(sacc[j][3] - mn1);
            rs0 += e0 + e1;
            rs1 += e2 + e3;
            p0[j] = h2pack(e0, e1);
            p1[j] = h2pack(e2, e3);
        }
#pragma unroll
        for (int off = 1; off < 4; off <<= 1) {
            rs0 += __shfl_xor_sync(0xffffffffu, rs0, off);
            rs1 += __shfl_xor_sync(0xffffffffu, rs1, off);
        }
        l0 = l0 * cr0 + rs0;
        l1 = l1 * cr1 + rs1;
        m0r = mn0;
        m1r = mn1;
#pragma unroll
        for (int j = 0; j < 16; j++) {
            oacc[j][0] *= cr0; oacc[j][1] *= cr0;
            oacc[j][2] *= cr1; oacc[j][3] *= cr1;
        }

        // ---- PV: fp16 m16n8k16, k=64 -> 4 k-steps; A from registers ----
#pragma unroll
        for (int kc = 0; kc < 4; kc++) {
            uint32_t a[4];
            a[0] = p0[2 * kc];
            a[1] = p1[2 * kc];
            a[2] = p0[2 * kc + 1];
            a[3] = p1[2 * kc + 1];
            const int row0 = kc * 8 + tig, row1 = row0 + 4;
            uint32_t vb0[16], vb1[16];
#pragma unroll
            for (int jq = 0; jq < 4; jq++) {
                *(uint4*)&vb0[jq * 4] = *(uint4*)&VsSt[row0 * 132 + g * 16 + jq * 4];
                *(uint4*)&vb1[jq * 4] = *(uint4*)&VsSt[row1 * 132 + g * 16 + jq * 4];
            }
#pragma unroll
            for (int j = 0; j < 16; j++)
                mma16h(oacc[j], a, vb0[j], vb1[j]);
        }
        __syncthreads();
    }

    // epilogue: write pre-split fp16 hi/lo tile-image directly
    float inv0 = 1.0f / l0, inv1 = 1.0f / l1;
#pragma unroll
    for (int j = 0; j < 16; j++) {
        int c = h * 128 + j * 8 + 2 * tig;
        float a0 = oacc[j][0] * inv0, a1 = oacc[j][1] * inv0;
        float b0v = oacc[j][2] * inv1, b1v = oacc[j][3] * inv1;
        size_t cb = (size_t)(q0 >> 7) * TILE_ELEMS + (size_t)(c >> 5) * SLAB_ELEMS
                  + (c & 31);
        size_t off0 = cb + r0 * 40;
        size_t off1 = cb + r1 * 40;
        *(uint32_t*)&oh[off0] = h2pack(a0, a1);
        *(uint32_t*)&ol[off0] = h2pack(hres(a0), hres(a1));
        *(uint32_t*)&oh[off1] = h2pack(b0v, b1v);
        *(uint32_t*)&ol[off1] = h2pack(hres(b0v), hres(b1v));
    }
}

// ---------------------------------------------------------------------------
extern "C" void kernel_launch(void* const* d_in, const int* in_sizes, int n_in,
                              void* d_out, int out_size)
{
    const float* x    = (const float*)d_in[0];
    const float* rope = (const float*)d_in[1];
    const float* Wq   = (const float*)d_in[2];
    const float* bq   = (const float*)d_in[3];
    const float* Wk   = (const float*)d_in[4];
    const float* bk   = (const float*)d_in[5];
    const float* Wv   = (const float*)d_in[6];
    const float* bv   = (const float*)d_in[7];
    const float* qn_w = (const float*)d_in[8];
    const float* kn_w = (const float*)d_in[9];
    const float* Wo   = (const float*)d_in[10];
    const float* bo   = (const float*)d_in[11];
    float* out = (float*)d_out;

    float* qp;
    uint32_t *kp, *vp;
    __half *xh, *xl, *ah, *al, *wq, *wk, *wv, *wo;
    cudaGetSymbolAddress((void**)&qp, g_q);
    cudaGetSymbolAddress((void**)&kp, g_k);
    cudaGetSymbolAddress((void**)&vp, g_v);
    cudaGetSymbolAddress((void**)&xh, g_xh);
    cudaGetSymbolAddress((void**)&xl, g_xl);
    cudaGetSymbolAddress((void**)&ah, g_ah);
    cudaGetSymbolAddress((void**)&al, g_al);
    cudaGetSymbolAddress((void**)&wq, g_wq);
    cudaGetSymbolAddress((void**)&wk, g_wk);
    cudaGetSymbolAddress((void**)&wv, g_wv);
    cudaGetSymbolAddress((void**)&wo, g_wo);

    const int smem_gemm = 67584;   // max(2*30720 stages, Cs 128*132*4)
    const int smem_attn = 68608;   // K 2*17408 + V 2*16896
    cudaFuncSetAttribute(gemm_blk, cudaFuncAttributeMaxDynamicSharedMemorySize,
                         smem_gemm);
    cudaFuncSetAttribute(flash_attn_tc, cudaFuncAttributeMaxDynamicSharedMemorySize,
                         smem_attn);

    split_a16<<<8192, 256>>>(x, xh, xl);
    split_w16<<<4096, 256>>>(Wq, wq);
    split_w16<<<4096, 256>>>(Wk, wk);
    split_w16<<<4096, 256>>>(Wv, wv);
    split_w16<<<4096, 256>>>(Wo, wo);

    dim3 ggrid(CC / 128, SS / 128);
    gemm_blk<<<ggrid, 256, smem_gemm>>>(xh, xl, wq, bq, qp, nullptr, qn_w, rope, 1);
    gemm_blk<<<ggrid, 256, smem_gemm>>>(xh, xl, wk, bk, nullptr, kp, kn_w, rope, 2);
    gemm_blk<<<ggrid, 256, smem_gemm>>>(xh, xl, wv, bv, nullptr, vp, nullptr, nullptr, 3);

    dim3 agrid(SS / 128, HH);
    flash_attn_tc<<<agrid, 256, smem_attn>>>(qp, kp, vp, ah, al);

    gemm_blk<<<ggrid, 256, smem_gemm>>>(ah, al, wo, bo, out, nullptr, nullptr, nullptr, 0);
}